// round 7
// baseline (speedup 1.0000x reference)
#include <cuda_runtime.h>
#include <cuda_bf16.h>
#include <cstdint>

// Problem constants
#define B_  64
#define S_  2048
#define E_  256
#define H_  256

#define NCONS 64          // consumer CTAs (one per batch)
#define NPROD 84          // producer CTAs
#define NCTAS (NCONS + NPROD)

// Scratch (device-global: runtime allocation is forbidden)
__device__ float g_xw[(size_t)B_ * S_ * H_];   // 128 MB: xw[b,s,h]
__device__ float g_UwT[H_ * H_];               // UwT[k][h] = Uw[h][k]
__device__ float g_WwT[E_ * H_];               // WwT[e][h] = Ww[h][e]
__device__ int   g_flag[S_];                   // per-timestep ready flags

__device__ __forceinline__ int ld_acquire_gpu(const int* p) {
    int v;
    asm volatile("ld.acquire.gpu.global.b32 %0, [%1];" : "=r"(v) : "l"(p) : "memory");
    return v;
}
__device__ __forceinline__ void st_release_gpu(int* p, int v) {
    asm volatile("st.release.gpu.global.b32 [%0], %1;" :: "l"(p), "r"(v) : "memory");
}
__device__ __forceinline__ float ld_cg_f(const float* p) {
    float v;
    asm volatile("ld.global.cg.f32 %0, [%1];" : "=f"(v) : "l"(p) : "memory");
    return v;
}

// Fast tanh: 1 - 2/(e^{2x}+1). |err| ~1e-6; exact saturation at +/-inf.
__device__ __forceinline__ float fast_tanh(float x) {
    float e = __expf(2.0f * x);
    float r;
    asm("rcp.approx.f32 %0, %1;" : "=f"(r) : "f"(e + 1.0f));
    return fmaf(-2.0f, r, 1.0f);
}

// ---------------------------------------------------------------------------
// prep: transpose Uw and Ww, zero flags
// ---------------------------------------------------------------------------
__global__ void prep(const float* __restrict__ Uw, const float* __restrict__ Ww) {
    int k = blockIdx.x;
    int h = threadIdx.x;
    g_UwT[k * H_ + h] = Uw[h * H_ + k];
    g_WwT[k * H_ + h] = Ww[h * E_ + k];
    if (k < 8) g_flag[k * H_ + h] = 0;   // 8*256 = 2048 flags
}

// ---------------------------------------------------------------------------
// Fused persistent kernel, 512 threads/CTA:
//   64 consumer CTAs (512 active: k-split-2 GEMV per batch)
//   84 producer CTAs (256 active: one 64x256x256 GEMM per timestep)
// ---------------------------------------------------------------------------
#define UREG 88                        // per-thread register-resident u values
#define USMH (128 - UREG)              // 40 per-thread smem u values (per k-half)

// smem floats: [ su2: 2 halves * (USMH/2) pairs * H_ * 2 ][ vsm: 2*H_ ][ psm: H_ ]
#define SU2_F   (USMH * H_ * 2)        // 40*256*2 = 20480 floats
#define SMEM_FLOATS (SU2_F + 2 * H_ + H_)
#define SMEM_BYTES  (SMEM_FLOATS * 4)  // 84992 B

#define PK 16
#define APAD 4
#define BPAD 4

__global__ __launch_bounds__(512, 1)
void fused(const float* __restrict__ x,       // [B,S,E]
           const float* __restrict__ Wb,      // [H]
           const float* __restrict__ Ub,      // [H]
           float* __restrict__ Out,           // [B,S,H]
           float* __restrict__ Tfin) {        // [B,H]
    extern __shared__ float sm[];
    const int tid = threadIdx.x;

    if (blockIdx.x >= NCONS) {
        // ================= PRODUCER (256 active threads) ==================
        if (tid >= 256) return;               // exited threads skip bar.sync

        const int p  = blockIdx.x - NCONS;
        float* As = sm;                                   // [PK][64+APAD]
        float* Bs = sm + PK * (64 + APAD);                // [PK][256+BPAD]
        const int ASTR = 64 + APAD;
        const int BSTR = H_ + BPAD;

        const int tx = tid & 15;                           // h quad group
        const int ty = tid >> 4;                           // b quad group
        const int arow = tid >> 2, akq = tid & 3;          // A-tile loads
        const int bk = tid >> 4, bh0 = (tid & 15) * 16;    // B-tile loads

        float4 bias[4];
        #pragma unroll
        for (int q = 0; q < 4; q++)
            bias[q] = *(const float4*)&Wb[tx * 4 + 64 * q];

        for (int s = p; s < S_; s += NPROD) {
            float acc[4][16] = {};

            const float* xs = x + (size_t)s * E_;
            float4 ra  = *(const float4*)&xs[(size_t)arow * S_ * E_ + akq * 4];
            float4 rb0 = *(const float4*)&g_WwT[bk * H_ + bh0 + 0];
            float4 rb1 = *(const float4*)&g_WwT[bk * H_ + bh0 + 4];
            float4 rb2 = *(const float4*)&g_WwT[bk * H_ + bh0 + 8];
            float4 rb3 = *(const float4*)&g_WwT[bk * H_ + bh0 + 12];

            for (int k0 = 0; k0 < E_; k0 += PK) {
                As[(akq * 4 + 0) * ASTR + arow] = ra.x;
                As[(akq * 4 + 1) * ASTR + arow] = ra.y;
                As[(akq * 4 + 2) * ASTR + arow] = ra.z;
                As[(akq * 4 + 3) * ASTR + arow] = ra.w;
                *(float4*)&Bs[bk * BSTR + bh0 + 0]  = rb0;
                *(float4*)&Bs[bk * BSTR + bh0 + 4]  = rb1;
                *(float4*)&Bs[bk * BSTR + bh0 + 8]  = rb2;
                *(float4*)&Bs[bk * BSTR + bh0 + 12] = rb3;
                __syncthreads();

                if (k0 + PK < E_) {
                    const int kn = k0 + PK;
                    ra  = *(const float4*)&xs[(size_t)arow * S_ * E_ + kn + akq * 4];
                    rb0 = *(const float4*)&g_WwT[(kn + bk) * H_ + bh0 + 0];
                    rb1 = *(const float4*)&g_WwT[(kn + bk) * H_ + bh0 + 4];
                    rb2 = *(const float4*)&g_WwT[(kn + bk) * H_ + bh0 + 8];
                    rb3 = *(const float4*)&g_WwT[(kn + bk) * H_ + bh0 + 12];
                }

                #pragma unroll
                for (int k = 0; k < PK; k++) {
                    float4 a  = *(const float4*)&As[k * ASTR + ty * 4];
                    float4 b0 = *(const float4*)&Bs[k * BSTR + tx * 4 + 0];
                    float4 b1 = *(const float4*)&Bs[k * BSTR + tx * 4 + 64];
                    float4 b2 = *(const float4*)&Bs[k * BSTR + tx * 4 + 128];
                    float4 b3 = *(const float4*)&Bs[k * BSTR + tx * 4 + 192];
                    float av;
                    #pragma unroll
                    for (int r = 0; r < 4; r++) {
                        av = (r == 0) ? a.x : (r == 1) ? a.y : (r == 2) ? a.z : a.w;
                        acc[r][0]  += av * b0.x; acc[r][1]  += av * b0.y;
                        acc[r][2]  += av * b0.z; acc[r][3]  += av * b0.w;
                        acc[r][4]  += av * b1.x; acc[r][5]  += av * b1.y;
                        acc[r][6]  += av * b1.z; acc[r][7]  += av * b1.w;
                        acc[r][8]  += av * b2.x; acc[r][9]  += av * b2.y;
                        acc[r][10] += av * b2.z; acc[r][11] += av * b2.w;
                        acc[r][12] += av * b3.x; acc[r][13] += av * b3.y;
                        acc[r][14] += av * b3.z; acc[r][15] += av * b3.w;
                    }
                }
                __syncthreads();
            }

            #pragma unroll
            for (int r = 0; r < 4; r++) {
                const int b = ty * 4 + r;
                float* row = g_xw + ((size_t)b * S_ + s) * H_;
                #pragma unroll
                for (int q = 0; q < 4; q++) {
                    float4 o = make_float4(acc[r][q * 4 + 0] + bias[q].x,
                                           acc[r][q * 4 + 1] + bias[q].y,
                                           acc[r][q * 4 + 2] + bias[q].z,
                                           acc[r][q * 4 + 3] + bias[q].w);
                    *(float4*)&row[tx * 4 + 64 * q] = o;
                }
            }
            __syncthreads();
            if (tid == 0) {
                __threadfence();
                st_release_gpu(&g_flag[s], 1);
            }
        }
        return;
    }

    // ================= CONSUMER: 512 threads, k-split 2 ===================
    float2* su2 = (float2*)sm;                 // [2*(USMH/2) pair-rows][H_]
    float*  vsm = sm + SU2_F;                  // 2 x H_ double buffer
    float*  psm = vsm + 2 * H_;                // H_ partials (from g==1)

    const int b = blockIdx.x;
    const int h = tid & (H_ - 1);
    const int g = tid >> 8;                    // k-half: 0 or 1
    const int kbase = g * 128;

    // Register-resident u: uw[j] = Uw[h][kbase + j], j in [0,UREG)
    float uw[UREG];
    #pragma unroll
    for (int j = 0; j < UREG; j++)
        uw[j] = g_UwT[(kbase + j) * H_ + h];

    // smem u: pair-rows for k in [kbase+UREG, kbase+128)
    const int g20 = g * (USMH / 2);
    for (int r = 0; r < USMH / 2; r++) {
        float a = g_UwT[(kbase + UREG + 2 * r + 0) * H_ + h];
        float c = g_UwT[(kbase + UREG + 2 * r + 1) * H_ + h];
        su2[(g20 + r) * H_ + h] = make_float2(a, c);
    }
    __syncthreads();

    const float ub = Ub[h];
    float t = 0.0f;

    const float* xwp = g_xw + (size_t)b * S_ * H_ + h;
    float*       op  = Out  + (size_t)b * S_ * H_ + h;

    float xv = 0.0f, xn = 0.0f;
    int   fspec = 1;
    if (g == 0) {
        while (ld_acquire_gpu(&g_flag[0]) == 0) { }
        xv = __ldcs(xwp);
        if (1 < S_) {
            fspec = ld_acquire_gpu(&g_flag[1]);
            xn    = __ldcs(xwp + H_);
        }
    }

    for (int s = 0; s < S_; s++) {
        // g0 publishes v_s = tanh(xw_s + t_{s-1})
        if (g == 0) {
            float v = fast_tanh(xv + t);
            vsm[(s & 1) * H_ + h] = v;
        }
        __syncthreads();

        // Both halves: half-dot over own k-range
        const float4* vq = (const float4*)(vsm + (s & 1) * H_) + g * 32;
        float a0 = 0.f, a1 = 0.f, a2 = 0.f, a3 = 0.f;
        float a4 = 0.f, a5 = 0.f, a6 = 0.f, a7 = 0.f;

        // Register section: 22 float4 groups (k_local 0..87)
        #pragma unroll
        for (int q = 0; q < UREG / 4; q++) {
            float4 vv = vq[q];
            const int j = 4 * q;
            a0 += uw[j + 0] * vv.x;
            a1 += uw[j + 1] * vv.y;
            a2 += uw[j + 2] * vv.z;
            a3 += uw[j + 3] * vv.w;
        }
        // smem section: 10 float4 groups (k_local 88..127), 2 pair-rows each
        const float2* up = su2 + g20 * H_ + h;
        #pragma unroll
        for (int rr = 0; rr < USMH / 2; rr += 2) {
            float4 vv = vq[(UREG + 2 * rr) / 4];
            float2 u0 = up[(rr + 0) * H_];
            float2 u1 = up[(rr + 1) * H_];
            a4 += u0.x * vv.x;
            a5 += u0.y * vv.y;
            a6 += u1.x * vv.z;
            a7 += u1.y * vv.w;
        }

        float a = ((a0 + a1) + (a2 + a3)) + ((a4 + a5) + (a6 + a7));
        if (g == 1) psm[h] = a;
        __syncthreads();

        if (g == 0) {
            t = a + psm[h] + ub;
            __stcs(&op[(size_t)s * H_], t);
            // advance speculative xw pipeline
            if (s + 1 < S_) {
                if (fspec == 0) {
                    while (ld_acquire_gpu(&g_flag[s + 1]) == 0) { }
                    xn = ld_cg_f(xwp + (size_t)(s + 1) * H_);
                }
                xv = xn;
                if (s + 2 < S_) {
                    fspec = ld_acquire_gpu(&g_flag[s + 2]);
                    xn    = __ldcs(xwp + (size_t)(s + 2) * H_);
                }
            }
        }
    }

    if (g == 0) Tfin[b * H_ + h] = t;
}

// ---------------------------------------------------------------------------
// Launcher
// ---------------------------------------------------------------------------
extern "C" void kernel_launch(void* const* d_in, const int* in_sizes, int n_in,
                              void* d_out, int out_size) {
    const float* x  = (const float*)d_in[0];   // [B,S,E]
    const float* Ww = (const float*)d_in[1];   // [H,E]
    const float* Wb = (const float*)d_in[2];   // [H]
    const float* Uw = (const float*)d_in[3];   // [H,H]
    const float* Ub = (const float*)d_in[4];   // [H]

    float* out  = (float*)d_out;
    float* tfin = out;                          // [B,H]
    float* O    = out + (size_t)B_ * H_;        // [B,S,H]

    cudaFuncSetAttribute(fused, cudaFuncAttributeMaxDynamicSharedMemorySize,
                         SMEM_BYTES);

    prep<<<H_, H_>>>(Uw, Ww);
    fused<<<NCTAS, 512, SMEM_BYTES>>>(x, Wb, Ub, O, tfin);
}

// round 8
// speedup vs baseline: 1.3199x; 1.3199x over previous
#include <cuda_runtime.h>
#include <cuda_bf16.h>
#include <cstdint>

// Problem constants
#define B_  64
#define S_  2048
#define E_  256
#define H_  256

#define NCONS 64          // consumer CTAs (one per batch)
#define NPROD 84          // producer CTAs
#define NCTAS (NCONS + NPROD)

// Scratch (device-global: runtime allocation is forbidden)
__device__ float g_xw[(size_t)B_ * S_ * H_];   // 128 MB: xw[b,s,h]
__device__ float g_UwT[H_ * H_];               // UwT[k][h] = Uw[h][k]
__device__ float g_WwT[E_ * H_];               // WwT[e][h] = Ww[h][e]
__device__ int   g_flag[S_];                   // per-timestep ready flags

__device__ __forceinline__ int ld_acquire_gpu(const int* p) {
    int v;
    asm volatile("ld.acquire.gpu.global.b32 %0, [%1];" : "=r"(v) : "l"(p) : "memory");
    return v;
}
__device__ __forceinline__ void st_release_gpu(int* p, int v) {
    asm volatile("st.release.gpu.global.b32 [%0], %1;" :: "l"(p), "r"(v) : "memory");
}
__device__ __forceinline__ float ld_cg_f(const float* p) {
    float v;
    asm volatile("ld.global.cg.f32 %0, [%1];" : "=f"(v) : "l"(p) : "memory");
    return v;
}

// Fast tanh: 1 - 2/(e^{2x}+1). |err| ~1e-6; exact saturation at +/-inf.
__device__ __forceinline__ float fast_tanh(float x) {
    float e = __expf(2.0f * x);
    float r;
    asm("rcp.approx.f32 %0, %1;" : "=f"(r) : "f"(e + 1.0f));
    return fmaf(-2.0f, r, 1.0f);
}

// ---------------------------------------------------------------------------
// prep: transpose Uw and Ww, zero flags
// ---------------------------------------------------------------------------
__global__ void prep(const float* __restrict__ Uw, const float* __restrict__ Ww) {
    int k = blockIdx.x;
    int h = threadIdx.x;
    g_UwT[k * H_ + h] = Uw[h * H_ + k];
    g_WwT[k * H_ + h] = Ww[h * E_ + k];
    if (k < 8) g_flag[k * H_ + h] = 0;   // 8*256 = 2048 flags
}

// ---------------------------------------------------------------------------
// Fused persistent kernel: 64 consumers + 84 producers, all co-resident.
// ---------------------------------------------------------------------------
#define UREG 192
#define USM  (H_ - UREG)               // 64 rows held in smem as 16 float4 rows

// smem floats: [ u4: 16 * H_ float4 ][ vsm: 2 * H_ float ]
#define SMEM_FLOATS (USM * H_ + 2 * H_)
#define SMEM_BYTES  (SMEM_FLOATS * 4)

#define PK 16
#define APAD 4
#define BPAD 4

__global__ __launch_bounds__(256, 1)
void fused(const float* __restrict__ x,       // [B,S,E]
           const float* __restrict__ Wb,      // [H]
           const float* __restrict__ Ub,      // [H]
           float* __restrict__ Out,           // [B,S,H]
           float* __restrict__ Tfin) {        // [B,H]
    extern __shared__ float sm[];
    const int tid = threadIdx.x;

    if (blockIdx.x >= NCONS) {
        // ================= PRODUCER: one 64x256x256 GEMM per timestep =====
        const int p  = blockIdx.x - NCONS;
        float* As = sm;                                   // [PK][64+APAD]
        float* Bs = sm + PK * (64 + APAD);                // [PK][256+BPAD]
        const int ASTR = 64 + APAD;
        const int BSTR = H_ + BPAD;

        const int tx = tid & 15;                           // h quad group
        const int ty = tid >> 4;                           // b quad group
        const int arow = tid >> 2, akq = tid & 3;          // A-tile loads
        const int bk = tid >> 4, bh0 = (tid & 15) * 16;    // B-tile loads

        float4 bias[4];
        #pragma unroll
        for (int q = 0; q < 4; q++)
            bias[q] = *(const float4*)&Wb[tx * 4 + 64 * q];

        for (int s = p; s < S_; s += NPROD) {
            float acc[4][16] = {};

            const float* xs = x + (size_t)s * E_;
            float4 ra  = *(const float4*)&xs[(size_t)arow * S_ * E_ + akq * 4];
            float4 rb0 = *(const float4*)&g_WwT[bk * H_ + bh0 + 0];
            float4 rb1 = *(const float4*)&g_WwT[bk * H_ + bh0 + 4];
            float4 rb2 = *(const float4*)&g_WwT[bk * H_ + bh0 + 8];
            float4 rb3 = *(const float4*)&g_WwT[bk * H_ + bh0 + 12];

            for (int k0 = 0; k0 < E_; k0 += PK) {
                As[(akq * 4 + 0) * ASTR + arow] = ra.x;
                As[(akq * 4 + 1) * ASTR + arow] = ra.y;
                As[(akq * 4 + 2) * ASTR + arow] = ra.z;
                As[(akq * 4 + 3) * ASTR + arow] = ra.w;
                *(float4*)&Bs[bk * BSTR + bh0 + 0]  = rb0;
                *(float4*)&Bs[bk * BSTR + bh0 + 4]  = rb1;
                *(float4*)&Bs[bk * BSTR + bh0 + 8]  = rb2;
                *(float4*)&Bs[bk * BSTR + bh0 + 12] = rb3;
                __syncthreads();

                if (k0 + PK < E_) {
                    const int kn = k0 + PK;
                    ra  = *(const float4*)&xs[(size_t)arow * S_ * E_ + kn + akq * 4];
                    rb0 = *(const float4*)&g_WwT[(kn + bk) * H_ + bh0 + 0];
                    rb1 = *(const float4*)&g_WwT[(kn + bk) * H_ + bh0 + 4];
                    rb2 = *(const float4*)&g_WwT[(kn + bk) * H_ + bh0 + 8];
                    rb3 = *(const float4*)&g_WwT[(kn + bk) * H_ + bh0 + 12];
                }

                #pragma unroll
                for (int k = 0; k < PK; k++) {
                    float4 a  = *(const float4*)&As[k * ASTR + ty * 4];
                    float4 b0 = *(const float4*)&Bs[k * BSTR + tx * 4 + 0];
                    float4 b1 = *(const float4*)&Bs[k * BSTR + tx * 4 + 64];
                    float4 b2 = *(const float4*)&Bs[k * BSTR + tx * 4 + 128];
                    float4 b3 = *(const float4*)&Bs[k * BSTR + tx * 4 + 192];
                    float av;
                    #pragma unroll
                    for (int r = 0; r < 4; r++) {
                        av = (r == 0) ? a.x : (r == 1) ? a.y : (r == 2) ? a.z : a.w;
                        acc[r][0]  += av * b0.x; acc[r][1]  += av * b0.y;
                        acc[r][2]  += av * b0.z; acc[r][3]  += av * b0.w;
                        acc[r][4]  += av * b1.x; acc[r][5]  += av * b1.y;
                        acc[r][6]  += av * b1.z; acc[r][7]  += av * b1.w;
                        acc[r][8]  += av * b2.x; acc[r][9]  += av * b2.y;
                        acc[r][10] += av * b2.z; acc[r][11] += av * b2.w;
                        acc[r][12] += av * b3.x; acc[r][13] += av * b3.y;
                        acc[r][14] += av * b3.z; acc[r][15] += av * b3.w;
                    }
                }
                __syncthreads();
            }

            #pragma unroll
            for (int r = 0; r < 4; r++) {
                const int b = ty * 4 + r;
                float* row = g_xw + ((size_t)b * S_ + s) * H_;
                #pragma unroll
                for (int q = 0; q < 4; q++) {
                    float4 o = make_float4(acc[r][q * 4 + 0] + bias[q].x,
                                           acc[r][q * 4 + 1] + bias[q].y,
                                           acc[r][q * 4 + 2] + bias[q].z,
                                           acc[r][q * 4 + 3] + bias[q].w);
                    *(float4*)&row[tx * 4 + 64 * q] = o;
                }
            }
            __syncthreads();
            if (tid == 0) {
                __threadfence();
                st_release_gpu(&g_flag[s], 1);
            }
        }
        return;
    }

    // ================= CONSUMER (per-batch recurrence) =====================
    float4* u4  = (float4*)sm;                 // [16][H_]: rows 192+4r..192+4r+3
    float*  vsm = sm + (size_t)USM * H_;       // 2 x H_ double buffer

    const int b = blockIdx.x;

    float uw[UREG];
    #pragma unroll
    for (int j = 0; j < UREG; j++)
        uw[j] = g_UwT[j * H_ + tid];

    // float4-pack smem u rows: u4[r][h] = (UwT[192+4r..192+4r+3][h])
    for (int r = 0; r < USM / 4; r++) {
        float4 u;
        u.x = g_UwT[(UREG + 4 * r + 0) * H_ + tid];
        u.y = g_UwT[(UREG + 4 * r + 1) * H_ + tid];
        u.z = g_UwT[(UREG + 4 * r + 2) * H_ + tid];
        u.w = g_UwT[(UREG + 4 * r + 3) * H_ + tid];
        u4[r * H_ + tid] = u;
    }
    __syncthreads();

    const float ub = Ub[tid];
    float t = 0.0f;

    const float* xwp = g_xw + (size_t)b * S_ * H_ + tid;
    float*       op  = Out  + (size_t)b * S_ * H_ + tid;

    while (ld_acquire_gpu(&g_flag[0]) == 0) { }
    float xv = __ldcs(xwp);

    const float4* up = u4 + tid;

    for (int s = 0; s < S_; s++) {
        float v = fast_tanh(xv + t);
        float* vb = vsm + (s & 1) * H_;
        vb[tid] = v;
        __syncthreads();

        // Speculative next-step fetch (validated after the dot)
        int   fspec = 1;
        float xn    = 0.0f;
        const float* xnp = xwp + (size_t)(s + 1) * H_;
        if (s + 1 < S_) {
            fspec = ld_acquire_gpu(&g_flag[s + 1]);
            xn    = __ldcs(xnp);
        }

        const float4* vq = (const float4*)vb;
        float a0 = ub, a1 = 0.f, a2 = 0.f, a3 = 0.f;
        float a4 = 0.f, a5 = 0.f, a6 = 0.f, a7 = 0.f;

        // 16 super-iterations: 3 register-u quads + 1 smem-u quad each.
        // LDS work is spread uniformly through the FMA stream so crossbar
        // and FMA pipes overlap instead of running in phases.
        #pragma unroll
        for (int it = 0; it < 16; it++) {
            float4 v0 = vq[3 * it + 0];
            float4 v1 = vq[3 * it + 1];
            float4 v2 = vq[3 * it + 2];
            float4 vs = vq[48 + it];
            float4 uv = up[it * H_];
            const int j = 12 * it;
            a0 += uw[j + 0]  * v0.x;  a1 += uw[j + 1]  * v0.y;
            a2 += uw[j + 2]  * v0.z;  a3 += uw[j + 3]  * v0.w;
            a4 += uw[j + 4]  * v1.x;  a5 += uw[j + 5]  * v1.y;
            a6 += uw[j + 6]  * v1.z;  a7 += uw[j + 7]  * v1.w;
            a0 += uw[j + 8]  * v2.x;  a1 += uw[j + 9]  * v2.y;
            a2 += uw[j + 10] * v2.z;  a3 += uw[j + 11] * v2.w;
            a4 += uv.x * vs.x;  a5 += uv.y * vs.y;
            a6 += uv.z * vs.z;  a7 += uv.w * vs.w;
        }

        t = ((a0 + a1) + (a2 + a3)) + ((a4 + a5) + (a6 + a7));
        __stcs(&op[(size_t)s * H_], t);

        // Validate speculation (slow path only during producer ramp)
        if (s + 1 < S_) {
            if (fspec == 0) {
                while (ld_acquire_gpu(&g_flag[s + 1]) == 0) { }
                xn = ld_cg_f(xnp);
            }
            xv = xn;
        }
    }

    Tfin[b * H_ + tid] = t;
}

// ---------------------------------------------------------------------------
// Launcher
// ---------------------------------------------------------------------------
extern "C" void kernel_launch(void* const* d_in, const int* in_sizes, int n_in,
                              void* d_out, int out_size) {
    const float* x  = (const float*)d_in[0];   // [B,S,E]
    const float* Ww = (const float*)d_in[1];   // [H,E]
    const float* Wb = (const float*)d_in[2];   // [H]
    const float* Uw = (const float*)d_in[3];   // [H,H]
    const float* Ub = (const float*)d_in[4];   // [H]

    float* out  = (float*)d_out;
    float* tfin = out;                          // [B,H]
    float* O    = out + (size_t)B_ * H_;        // [B,S,H]

    cudaFuncSetAttribute(fused, cudaFuncAttributeMaxDynamicSharedMemorySize,
                         SMEM_BYTES);

    prep<<<H_, H_>>>(Uw, Ww);
    fused<<<NCTAS, 256, SMEM_BYTES>>>(x, Wb, Ub, O, tfin);
}

// round 9
// speedup vs baseline: 1.4814x; 1.1223x over previous
#include <cuda_runtime.h>
#include <cuda_bf16.h>
#include <cstdint>

// Problem constants
#define B_  64
#define S_  2048
#define E_  256
#define H_  256

#define NCONS 64          // consumer CTAs (one per batch)
#define NPROD 48          // producer CTAs (reduced: power/clock headroom)
#define NCTAS (NCONS + NPROD)

// Scratch (device-global: runtime allocation is forbidden)
__device__ float g_xw[(size_t)B_ * S_ * H_];   // 128 MB: xw[b,s,h]
__device__ float g_UwT[H_ * H_];               // UwT[k][h] = Uw[h][k]
__device__ float g_WwT[E_ * H_];               // WwT[e][h] = Ww[h][e]
__device__ int   g_flag[S_];                   // per-timestep ready flags

__device__ __forceinline__ int ld_acquire_gpu(const int* p) {
    int v;
    asm volatile("ld.acquire.gpu.global.b32 %0, [%1];" : "=r"(v) : "l"(p) : "memory");
    return v;
}
__device__ __forceinline__ void st_release_gpu(int* p, int v) {
    asm volatile("st.release.gpu.global.b32 [%0], %1;" :: "l"(p), "r"(v) : "memory");
}
__device__ __forceinline__ float ld_cg_f(const float* p) {
    float v;
    asm volatile("ld.global.cg.f32 %0, [%1];" : "=f"(v) : "l"(p) : "memory");
    return v;
}

// Fast tanh: 1 - 2/(e^{2x}+1). |err| ~1e-6; exact saturation at +/-inf.
__device__ __forceinline__ float fast_tanh(float x) {
    float e = __expf(2.0f * x);
    float r;
    asm("rcp.approx.f32 %0, %1;" : "=f"(r) : "f"(e + 1.0f));
    return fmaf(-2.0f, r, 1.0f);
}

// ---------------------------------------------------------------------------
// prep: transpose Uw and Ww, zero flags
// ---------------------------------------------------------------------------
__global__ void prep(const float* __restrict__ Uw, const float* __restrict__ Ww) {
    int k = blockIdx.x;
    int h = threadIdx.x;
    g_UwT[k * H_ + h] = Uw[h * H_ + k];
    g_WwT[k * H_ + h] = Ww[h * E_ + k];
    if (k < 8) g_flag[k * H_ + h] = 0;   // 8*256 = 2048 flags
}

// ---------------------------------------------------------------------------
// Fused persistent kernel: 64 consumers + 48 producers, all co-resident.
// ---------------------------------------------------------------------------
#define UREG 192
#define USM  (H_ - UREG)

#define SCAN_SMEM_FLOATS (USM * H_ + 2 * H_)
#define SMEM_BYTES (SCAN_SMEM_FLOATS * 4)

#define PK 16
#define APAD 4
#define BPAD 4

__global__ __launch_bounds__(256, 1)
void fused(const float* __restrict__ x,       // [B,S,E]
           const float* __restrict__ Wb,      // [H]
           const float* __restrict__ Ub,      // [H]
           float* __restrict__ Out,           // [B,S,H]
           float* __restrict__ Tfin) {        // [B,H]
    extern __shared__ float sm[];
    const int tid = threadIdx.x;

    if (blockIdx.x >= NCONS) {
        // ================= PRODUCER: one 64x256x256 GEMM per timestep =====
        const int p  = blockIdx.x - NCONS;
        float* As = sm;                                   // [PK][64+APAD]
        float* Bs = sm + PK * (64 + APAD);                // [PK][256+BPAD]
        const int ASTR = 64 + APAD;
        const int BSTR = H_ + BPAD;

        const int tx = tid & 15;                           // h quad group
        const int ty = tid >> 4;                           // b quad group
        const int arow = tid >> 2, akq = tid & 3;          // A-tile loads
        const int bk = tid >> 4, bh0 = (tid & 15) * 16;    // B-tile loads

        float4 bias[4];
        #pragma unroll
        for (int q = 0; q < 4; q++)
            bias[q] = *(const float4*)&Wb[tx * 4 + 64 * q];

        for (int s = p; s < S_; s += NPROD) {
            float acc[4][16] = {};

            const float* xs = x + (size_t)s * E_;
            float4 ra  = *(const float4*)&xs[(size_t)arow * S_ * E_ + akq * 4];
            float4 rb0 = *(const float4*)&g_WwT[bk * H_ + bh0 + 0];
            float4 rb1 = *(const float4*)&g_WwT[bk * H_ + bh0 + 4];
            float4 rb2 = *(const float4*)&g_WwT[bk * H_ + bh0 + 8];
            float4 rb3 = *(const float4*)&g_WwT[bk * H_ + bh0 + 12];

            for (int k0 = 0; k0 < E_; k0 += PK) {
                As[(akq * 4 + 0) * ASTR + arow] = ra.x;
                As[(akq * 4 + 1) * ASTR + arow] = ra.y;
                As[(akq * 4 + 2) * ASTR + arow] = ra.z;
                As[(akq * 4 + 3) * ASTR + arow] = ra.w;
                *(float4*)&Bs[bk * BSTR + bh0 + 0]  = rb0;
                *(float4*)&Bs[bk * BSTR + bh0 + 4]  = rb1;
                *(float4*)&Bs[bk * BSTR + bh0 + 8]  = rb2;
                *(float4*)&Bs[bk * BSTR + bh0 + 12] = rb3;
                __syncthreads();

                if (k0 + PK < E_) {
                    const int kn = k0 + PK;
                    ra  = *(const float4*)&xs[(size_t)arow * S_ * E_ + kn + akq * 4];
                    rb0 = *(const float4*)&g_WwT[(kn + bk) * H_ + bh0 + 0];
                    rb1 = *(const float4*)&g_WwT[(kn + bk) * H_ + bh0 + 4];
                    rb2 = *(const float4*)&g_WwT[(kn + bk) * H_ + bh0 + 8];
                    rb3 = *(const float4*)&g_WwT[(kn + bk) * H_ + bh0 + 12];
                }

                #pragma unroll
                for (int k = 0; k < PK; k++) {
                    float4 a  = *(const float4*)&As[k * ASTR + ty * 4];
                    float4 b0 = *(const float4*)&Bs[k * BSTR + tx * 4 + 0];
                    float4 b1 = *(const float4*)&Bs[k * BSTR + tx * 4 + 64];
                    float4 b2 = *(const float4*)&Bs[k * BSTR + tx * 4 + 128];
                    float4 b3 = *(const float4*)&Bs[k * BSTR + tx * 4 + 192];
                    float av;
                    #pragma unroll
                    for (int r = 0; r < 4; r++) {
                        av = (r == 0) ? a.x : (r == 1) ? a.y : (r == 2) ? a.z : a.w;
                        acc[r][0]  += av * b0.x; acc[r][1]  += av * b0.y;
                        acc[r][2]  += av * b0.z; acc[r][3]  += av * b0.w;
                        acc[r][4]  += av * b1.x; acc[r][5]  += av * b1.y;
                        acc[r][6]  += av * b1.z; acc[r][7]  += av * b1.w;
                        acc[r][8]  += av * b2.x; acc[r][9]  += av * b2.y;
                        acc[r][10] += av * b2.z; acc[r][11] += av * b2.w;
                        acc[r][12] += av * b3.x; acc[r][13] += av * b3.y;
                        acc[r][14] += av * b3.z; acc[r][15] += av * b3.w;
                    }
                }
                __syncthreads();
            }

            #pragma unroll
            for (int r = 0; r < 4; r++) {
                const int b = ty * 4 + r;
                float* row = g_xw + ((size_t)b * S_ + s) * H_;
                #pragma unroll
                for (int q = 0; q < 4; q++) {
                    float4 o = make_float4(acc[r][q * 4 + 0] + bias[q].x,
                                           acc[r][q * 4 + 1] + bias[q].y,
                                           acc[r][q * 4 + 2] + bias[q].z,
                                           acc[r][q * 4 + 3] + bias[q].w);
                    *(float4*)&row[tx * 4 + 64 * q] = o;
                }
            }
            __syncthreads();
            if (tid == 0) {
                __threadfence();
                st_release_gpu(&g_flag[s], 1);
            }
        }
        return;
    }

    // ================= CONSUMER (per-batch recurrence) =====================
    float2* u2  = (float2*)sm;
    float*  vsm = sm + (size_t)USM * H_;

    const int b = blockIdx.x;

    float uw[UREG];
    #pragma unroll
    for (int j = 0; j < UREG; j++)
        uw[j] = g_UwT[j * H_ + tid];

    for (int r2 = 0; r2 < USM / 2; r2++) {
        float a = g_UwT[(UREG + 2 * r2 + 0) * H_ + tid];
        float c = g_UwT[(UREG + 2 * r2 + 1) * H_ + tid];
        u2[r2 * H_ + tid] = make_float2(a, c);
    }
    __syncthreads();

    const float ub = Ub[tid];
    float t = 0.0f;

    const float* xwp = g_xw + (size_t)b * S_ * H_ + tid;
    float*       op  = Out  + (size_t)b * S_ * H_ + tid;

    while (ld_acquire_gpu(&g_flag[0]) == 0) { }
    float xv = __ldcs(xwp);

    for (int s = 0; s < S_; s++) {
        float v = fast_tanh(xv + t);
        float* vb = vsm + (s & 1) * H_;
        vb[tid] = v;
        __syncthreads();

        // Speculative next-step fetch: acquire flag + load xw; validate AFTER
        // the ~1500-cycle dot so neither latency is exposed.
        int   fspec = 1;
        float xn    = 0.0f;
        const float* xnp = xwp + (size_t)(s + 1) * H_;
        if (s + 1 < S_) {
            fspec = ld_acquire_gpu(&g_flag[s + 1]);
            xn    = __ldcs(xnp);
        }

        const float4* v4 = (const float4*)vb;
        float a0 = ub, a1 = 0.f, a2 = 0.f, a3 = 0.f;
        float a4 = 0.f, a5 = 0.f, a6 = 0.f, a7 = 0.f;

        float4 vA = v4[0];
        float4 vB = v4[1];

        // Register section: rows [0,192) = 48 float4 groups, pipelined
        #pragma unroll
        for (int q = 0; q < 48; q += 2) {
            float4 nA = v4[q + 2];
            float4 nB = v4[q + 3];
            const int j = 4 * q;
            a0 += uw[j + 0] * vA.x;  a1 += uw[j + 1] * vA.y;
            a2 += uw[j + 2] * vA.z;  a3 += uw[j + 3] * vA.w;
            a4 += uw[j + 4] * vB.x;  a5 += uw[j + 5] * vB.y;
            a6 += uw[j + 6] * vB.z;  a7 += uw[j + 7] * vB.w;
            vA = nA; vB = nB;
        }

        // Shared-memory section: rows [192,256) = 16 float4 groups
        const float2* up = u2 + tid;
        #pragma unroll
        for (int q = 48; q < 64; q += 2) {
            float4 nA, nB;
            if (q + 2 < 64) { nA = v4[q + 2]; nB = v4[q + 3]; }
            else            { nA = vA;        nB = vB;        }
            const int r2b = (4 * q - UREG) >> 1;
            float2 u0 = up[(r2b + 0) * H_];
            float2 u1 = up[(r2b + 1) * H_];
            float2 uu = up[(r2b + 2) * H_];
            float2 u3 = up[(r2b + 3) * H_];
            a0 += u0.x * vA.x;  a1 += u0.y * vA.y;
            a2 += u1.x * vA.z;  a3 += u1.y * vA.w;
            a4 += uu.x * vB.x;  a5 += uu.y * vB.y;
            a6 += u3.x * vB.z;  a7 += u3.y * vB.w;
            vA = nA; vB = nB;
        }

        t = ((a0 + a1) + (a2 + a3)) + ((a4 + a5) + (a6 + a7));
        __stcs(&op[(size_t)s * H_], t);

        // Validate speculation (slow path only during producer ramp)
        if (s + 1 < S_) {
            if (fspec == 0) {
                while (ld_acquire_gpu(&g_flag[s + 1]) == 0) { }
                xn = ld_cg_f(xnp);
            }
            xv = xn;
        }
    }

    Tfin[b * H_ + tid] = t;
}

// ---------------------------------------------------------------------------
// Launcher
// ---------------------------------------------------------------------------
extern "C" void kernel_launch(void* const* d_in, const int* in_sizes, int n_in,
                              void* d_out, int out_size) {
    const float* x  = (const float*)d_in[0];   // [B,S,E]
    const float* Ww = (const float*)d_in[1];   // [H,E]
    const float* Wb = (const float*)d_in[2];   // [H]
    const float* Uw = (const float*)d_in[3];   // [H,H]
    const float* Ub = (const float*)d_in[4];   // [H]

    float* out  = (float*)d_out;
    float* tfin = out;                          // [B,H]
    float* O    = out + (size_t)B_ * H_;        // [B,S,H]

    cudaFuncSetAttribute(fused, cudaFuncAttributeMaxDynamicSharedMemorySize,
                         SMEM_BYTES);

    prep<<<H_, H_>>>(Uw, Ww);
    fused<<<NCTAS, 256, SMEM_BYTES>>>(x, Wb, Ub, O, tfin);
}